// round 9
// baseline (speedup 1.0000x reference)
#include <cuda_runtime.h>
#include <cuda_fp16.h>
#include <cstdint>

// Problem constants (fixed by the reference)
#define NNODES 50000
#define NREL   8
#define DIM    128
#define NEDGES 800000
#define NZ     9                       // z=0: root path, z=1..8: relations 0..7
#define MTILE  128
#define NRB    ((NNODES + MTILE - 1) / MTILE)   // 391 row blocks
#define SEG    (NREL * NNODES)         // 400000
#define NSCAN_BLK ((SEG + 511) / 512)  // 782

// full-K smem tiles viewed as u32 (half2): 64 u32/row padded to 68 -> conflict-free
#define KSTR 68
#define A_SM (MTILE * KSTR)
#define B_SM (MTILE * KSTR)
#define GEMM_SMEM ((A_SM + 2 * B_SM) * 4)   // 104448 B

// ---------------- scratch (static device globals; no allocation) ----------------
__device__ __half g_Y16[(size_t)NREL * NNODES * DIM];
__device__ float  g_acc[(size_t)NNODES * DIM];
__device__ __half g_A16[(size_t)NNODES * DIM];
__device__ __half g_WH[2 * NZ * DIM * DIM];   // [layer][z][n][k], z=0 root
__device__ int    g_cnt[SEG];
__device__ int    g_incl[SEG];
__device__ int    g_off[SEG + 1];
__device__ int    g_cursor[SEG];
__device__ int    g_binh[NEDGES];
__device__ int    g_bsum[1024];

// ---------------- helpers ----------------
__device__ __forceinline__ void mma_f16(float* c, const uint32_t* a, const uint32_t* b) {
    asm volatile(
        "mma.sync.aligned.m16n8k16.row.col.f32.f16.f16.f32 "
        "{%0,%1,%2,%3}, {%4,%5,%6,%7}, {%8,%9}, {%0,%1,%2,%3};"
        : "+f"(c[0]), "+f"(c[1]), "+f"(c[2]), "+f"(c[3])
        : "r"(a[0]), "r"(a[1]), "r"(a[2]), "r"(a[3]), "r"(b[0]), "r"(b[1]));
}
__device__ __forceinline__ void cp_async16(uint32_t daddr, const void* src, int srcbytes) {
    asm volatile("cp.async.cg.shared.global [%0], [%1], 16, %2;"
                 :: "r"(daddr), "l"(src), "r"(srcbytes));
}
#define CP_COMMIT() asm volatile("cp.async.commit_group;" ::: "memory")
#define CP_WAIT1()  asm volatile("cp.async.wait_group 1;" ::: "memory")
#define CP_WAIT0()  asm volatile("cp.async.wait_group 0;" ::: "memory")

// ---------------- setup / binning kernels ----------------
__global__ void k_zero_cnt(int* __restrict__ cnt, int n) {
    int i = blockIdx.x * blockDim.x + threadIdx.x;
    if (i < n) cnt[i] = 0;
}
__global__ void k_count(const int* __restrict__ r, const int* __restrict__ t,
                        int* __restrict__ cnt, int E) {
    int e = blockIdx.x * blockDim.x + threadIdx.x;
    if (e < E) atomicAdd(&cnt[r[e] * NNODES + t[e]], 1);
}
__global__ void k_scan1(const int* __restrict__ cnt, int* __restrict__ incl,
                        int* __restrict__ bsum, int n) {
    __shared__ int sm[512];
    int tid = threadIdx.x;
    int gid = blockIdx.x * 512 + tid;
    sm[tid] = (gid < n) ? cnt[gid] : 0;
    __syncthreads();
#pragma unroll
    for (int d = 1; d < 512; d <<= 1) {
        int add = (tid >= d) ? sm[tid - d] : 0;
        __syncthreads();
        sm[tid] += add;
        __syncthreads();
    }
    if (gid < n) incl[gid] = sm[tid];
    if (tid == 511) bsum[blockIdx.x] = sm[511];
}
__global__ void k_scan2(int* __restrict__ bsum, int nb) {
    __shared__ int sm[1024];
    int tid = threadIdx.x;
    sm[tid] = (tid < nb) ? bsum[tid] : 0;
    __syncthreads();
#pragma unroll
    for (int d = 1; d < 1024; d <<= 1) {
        int add = (tid >= d) ? sm[tid - d] : 0;
        __syncthreads();
        sm[tid] += add;
        __syncthreads();
    }
    if (tid < nb) bsum[tid] = sm[tid];
}
__global__ void k_scan3(const int* __restrict__ cnt, const int* __restrict__ incl,
                        const int* __restrict__ bsum, int* __restrict__ off,
                        int* __restrict__ cursor, int n) {
    int gid = blockIdx.x * 512 + threadIdx.x;
    if (gid >= n) return;
    int base = (blockIdx.x > 0) ? bsum[blockIdx.x - 1] : 0;
    int ex = base + incl[gid] - cnt[gid];
    off[gid] = ex;
    cursor[gid] = ex;
    if (gid == n - 1) off[n] = base + incl[gid];
}
__global__ void k_bin(const int* __restrict__ h, const int* __restrict__ r,
                      const int* __restrict__ t, int* __restrict__ cursor,
                      int* __restrict__ binh, int E) {
    int e = blockIdx.x * blockDim.x + threadIdx.x;
    if (e >= E) return;
    int seg = r[e] * NNODES + t[e];
    int pos = atomicAdd(&cursor[seg], 1);
    binh[pos] = h[e];
}

// WH both layers: [layer][z][n][k]; z=0 -> root, z>=1 -> W[z-1]; transposed + fp16
__global__ void k_wt2(const float* __restrict__ W1, const float* __restrict__ root1,
                      const float* __restrict__ W2, const float* __restrict__ root2,
                      __half* __restrict__ dst) {
    int idx = blockIdx.x * blockDim.x + threadIdx.x;
    if (idx >= 2 * NZ * DIM * DIM) return;
    int zz = idx >> 14;
    int layer = zz / NZ, z = zz % NZ;
    int rem = idx & 16383;
    int n = rem >> 7, k = rem & 127;
    const float* src = (z == 0) ? (layer ? root2 : root1)
                                : ((layer ? W2 : W1) + ((size_t)(z - 1) << 14));
    dst[idx] = __float2half_rn(src[k * DIM + n]);
}

__global__ void k_cvt16(const float2* __restrict__ in, uint32_t* __restrict__ out, int n2) {
    int i = blockIdx.x * blockDim.x + threadIdx.x;
    if (i < n2) {
        float2 v = in[i];
        __half2 hv = __floats2half2_rn(v.x, v.y);
        out[i] = *(uint32_t*)&hv;
    }
}

// ---------------- z-loop fp16 GEMM over z in [z0, z1) ----------------
// z==0 -> fp32 acc + bias; z>=1 -> fp16 Y[z-1].
__global__ __launch_bounds__(256, 2) void k_gemm_z(
    const __half* __restrict__ X, const __half* __restrict__ WH,
    const float* __restrict__ bias, __half* __restrict__ Y,
    float* __restrict__ acc, int Nn, int z0, int z1)
{
    extern __shared__ uint32_t sm[];
    uint32_t* As = sm;
    uint32_t* Bs = sm + A_SM;

    const int tid = threadIdx.x;
    const int wid = tid >> 5;
    const int lane = tid & 31;
    const int g = lane >> 2;
    const int q = lane & 3;
    const int warp_m = wid & 3;
    const int warp_n = wid >> 2;
    const int row0 = blockIdx.x * MTILE;

    const uint32_t abase = (uint32_t)__cvta_generic_to_shared(As);
    const uint32_t bbase = (uint32_t)__cvta_generic_to_shared(Bs);

#pragma unroll
    for (int l = 0; l < 8; l++) {
        int lin = tid + 256 * l;
        int row = lin >> 4, seg = lin & 15;
        int gr = row0 + row;
        int ok = (gr < Nn) ? 16 : 0;
        int grc = (gr < Nn) ? gr : (Nn - 1);
        cp_async16(abase + (uint32_t)(row * KSTR + seg * 4) * 4,
                   X + (size_t)grc * DIM + seg * 8, ok);
    }
    CP_COMMIT();

    auto fill_B = [&](int buf, int z) {
        const __half* Bz = WH + ((size_t)z << 14);
        uint32_t base = bbase + (uint32_t)buf * B_SM * 4;
#pragma unroll
        for (int l = 0; l < 8; l++) {
            int lin = tid + 256 * l;
            int row = lin >> 4, seg = lin & 15;
            cp_async16(base + (uint32_t)(row * KSTR + seg * 4) * 4,
                       Bz + (size_t)row * DIM + seg * 8, 16);
        }
        CP_COMMIT();
    };
    fill_B(0, z0);

    const int ar = warp_m * 32 + g;
    const int bn = warp_n * 64 + g;

#pragma unroll 1
    for (int z = z0; z < z1; z++) {
        if (z < z1 - 1) { fill_B((z - z0 + 1) & 1, z + 1); CP_WAIT1(); }
        else            { CP_WAIT0(); }
        __syncthreads();

        const uint32_t* B_ = Bs + ((z - z0) & 1) * B_SM;

        float cfrag[2][8][4];
#pragma unroll
        for (int mt = 0; mt < 2; mt++)
#pragma unroll
            for (int nt = 0; nt < 8; nt++)
#pragma unroll
                for (int i = 0; i < 4; i++) cfrag[mt][nt][i] = 0.0f;

#pragma unroll
        for (int ks = 0; ks < 8; ks++) {
            const int ko = ks * 8 + q;
            uint32_t a[2][4];
#pragma unroll
            for (int mt = 0; mt < 2; mt++) {
                int base = (ar + mt * 16) * KSTR + ko;
                a[mt][0] = As[base];
                a[mt][1] = As[base + 8 * KSTR];
                a[mt][2] = As[base + 4];
                a[mt][3] = As[base + 8 * KSTR + 4];
            }
            uint32_t b[8][2];
#pragma unroll
            for (int nt = 0; nt < 8; nt++) {
                int base = (bn + nt * 8) * KSTR + ko;
                b[nt][0] = B_[base];
                b[nt][1] = B_[base + 4];
            }
#pragma unroll
            for (int mt = 0; mt < 2; mt++)
#pragma unroll
                for (int nt = 0; nt < 8; nt++)
                    mma_f16(cfrag[mt][nt], a[mt], b[nt]);
        }
        __syncthreads();

        if (z >= 1) {
            __half* C = Y + (size_t)(z - 1) * Nn * DIM;
#pragma unroll
            for (int mt = 0; mt < 2; mt++)
#pragma unroll
                for (int half_ = 0; half_ < 2; half_++) {
                    int row = row0 + warp_m * 32 + mt * 16 + half_ * 8 + g;
                    if (row >= Nn) continue;
#pragma unroll
                    for (int nt = 0; nt < 8; nt++) {
                        int col = warp_n * 64 + nt * 8 + 2 * q;
                        __half2 hv = __floats2half2_rn(cfrag[mt][nt][half_ * 2 + 0],
                                                       cfrag[mt][nt][half_ * 2 + 1]);
                        *(uint32_t*)&C[(size_t)row * DIM + col] = *(uint32_t*)&hv;
                    }
                }
        } else {
#pragma unroll
            for (int mt = 0; mt < 2; mt++)
#pragma unroll
                for (int half_ = 0; half_ < 2; half_++) {
                    int row = row0 + warp_m * 32 + mt * 16 + half_ * 8 + g;
                    if (row >= Nn) continue;
#pragma unroll
                    for (int nt = 0; nt < 8; nt++) {
                        int col = warp_n * 64 + nt * 8 + 2 * q;
                        float2 v;
                        v.x = cfrag[mt][nt][half_ * 2 + 0] + bias[col];
                        v.y = cfrag[mt][nt][half_ * 2 + 1] + bias[col + 1];
                        *(float2*)&acc[(size_t)row * DIM + col] = v;
                    }
                }
        }
    }
}

// ---------------- aggregation (split): one warp per target node, atomic-free ----------------
// PHASE 0: relations 0..3, acc[t] += partial means (in place).
// PHASE 1: relations 4..7, relu(acc + means) -> fp16 A16.
// PHASE 2: relations 4..7, block-reduced column mean of (acc + means) -> atomicAdd out.
template <int PHASE>
__global__ __launch_bounds__(256) void k_agg(
    const __half* __restrict__ Y, const int* __restrict__ off,
    const int* __restrict__ binh, float* __restrict__ acc,
    uint32_t* __restrict__ out16, float* __restrict__ outf)
{
    __shared__ float bsum[8][DIM];
    const int wid = threadIdx.x >> 5;
    const int lane = threadIdx.x & 31;
    const int t = blockIdx.x * 8 + wid;        // NNODES % 8 == 0

    const int R0 = (PHASE == 0) ? 0 : 4;

    float4 a4 = ((const float4*)(acc + (size_t)t * DIM))[lane];

#pragma unroll
    for (int ri = 0; ri < 4; ri++) {
        int rr = R0 + ri;
        int seg = rr * NNODES + t;
        int s = __ldg(&off[seg]);
        int e = __ldg(&off[seg + 1]);
        if (e > s) {
            float4 sum = make_float4(0.f, 0.f, 0.f, 0.f);
            const __half* Yr = Y + (size_t)rr * NNODES * DIM;
            for (int i = s; i < e; i++) {
                int hh = __ldg(&binh[i]);
                uint2 v = ((const uint2*)(Yr + (size_t)hh * DIM))[lane];
                __half2* hp = (__half2*)&v;
                float2 f0 = __half22float2(hp[0]);
                float2 f1 = __half22float2(hp[1]);
                sum.x += f0.x; sum.y += f0.y; sum.z += f1.x; sum.w += f1.y;
            }
            float w = 1.0f / (float)(e - s);
            a4.x += sum.x * w; a4.y += sum.y * w;
            a4.z += sum.z * w; a4.w += sum.w * w;
        }
    }

    if (PHASE == 0) {
        ((float4*)(acc + (size_t)t * DIM))[lane] = a4;
    } else if (PHASE == 1) {
        __half2 h0 = __floats2half2_rn(fmaxf(a4.x, 0.f), fmaxf(a4.y, 0.f));
        __half2 h1 = __floats2half2_rn(fmaxf(a4.z, 0.f), fmaxf(a4.w, 0.f));
        uint2 o;
        o.x = *(uint32_t*)&h0;
        o.y = *(uint32_t*)&h1;
        ((uint2*)(out16 + (size_t)t * (DIM / 2)))[lane] = o;
    } else {
        bsum[wid][lane * 4 + 0] = a4.x;
        bsum[wid][lane * 4 + 1] = a4.y;
        bsum[wid][lane * 4 + 2] = a4.z;
        bsum[wid][lane * 4 + 3] = a4.w;
        __syncthreads();
        int c = threadIdx.x;
        if (c < DIM) {
            float s = 0.0f;
#pragma unroll
            for (int w2 = 0; w2 < 8; w2++) s += bsum[w2][c];
            atomicAdd(&outf[c], s * (1.0f / (float)NNODES));
        }
    }
}

__global__ void k_zero_out(float* __restrict__ out) { out[threadIdx.x] = 0.0f; }

// ---------------- launch ----------------
extern "C" void kernel_launch(void* const* d_in, const int* in_sizes, int n_in,
                              void* d_out, int out_size) {
    const int*   h     = (const int*)d_in[0];
    const int*   r     = (const int*)d_in[1];
    const int*   t     = (const int*)d_in[2];
    const float* x_emb = (const float*)d_in[3];
    const float* W1    = (const float*)d_in[4];
    const float* root1 = (const float*)d_in[5];
    const float* b1    = (const float*)d_in[6];
    const float* W2    = (const float*)d_in[7];
    const float* root2 = (const float*)d_in[8];
    const float* b2    = (const float*)d_in[9];
    float* out = (float*)d_out;

    __half *Y16, *A16, *WH;
    float *acc;
    int *cnt, *incl, *off, *cursor, *binh, *bsum;
    cudaGetSymbolAddress((void**)&Y16,    g_Y16);
    cudaGetSymbolAddress((void**)&acc,    g_acc);
    cudaGetSymbolAddress((void**)&A16,    g_A16);
    cudaGetSymbolAddress((void**)&WH,     g_WH);
    cudaGetSymbolAddress((void**)&cnt,    g_cnt);
    cudaGetSymbolAddress((void**)&incl,   g_incl);
    cudaGetSymbolAddress((void**)&off,    g_off);
    cudaGetSymbolAddress((void**)&cursor, g_cursor);
    cudaGetSymbolAddress((void**)&binh,   g_binh);
    cudaGetSymbolAddress((void**)&bsum,   g_bsum);

    const int E = NEDGES, Nn = NNODES;
    const int n2 = Nn * DIM / 2;
    const int agg_blocks = Nn / 8;   // 6250
    const __half* WH2 = WH + (size_t)NZ * DIM * DIM;

    // one-time resources (created on the first, uncaptured call; reused under capture)
    static cudaStream_t s2 = nullptr;
    static cudaEvent_t evFork, evG1a, evA0, evG2a, evA1;
    if (!s2) {
        cudaFuncSetAttribute(k_gemm_z, cudaFuncAttributeMaxDynamicSharedMemorySize, GEMM_SMEM);
        cudaStreamCreateWithFlags(&s2, cudaStreamNonBlocking);
        cudaEventCreateWithFlags(&evFork, cudaEventDisableTiming);
        cudaEventCreateWithFlags(&evG1a,  cudaEventDisableTiming);
        cudaEventCreateWithFlags(&evA0,   cudaEventDisableTiming);
        cudaEventCreateWithFlags(&evG2a,  cudaEventDisableTiming);
        cudaEventCreateWithFlags(&evA1,   cudaEventDisableTiming);
    }

    // ---- fork: CSR build on s2, concurrent with weight prep + gemm1a ----
    cudaEventRecord(evFork, 0);
    cudaStreamWaitEvent(s2, evFork, 0);
    k_zero_cnt<<<(SEG + 255) / 256, 256, 0, s2>>>(cnt, SEG);
    k_count<<<(E + 255) / 256, 256, 0, s2>>>(r, t, cnt, E);
    k_scan1<<<NSCAN_BLK, 512, 0, s2>>>(cnt, incl, bsum, SEG);
    k_scan2<<<1, 1024, 0, s2>>>(bsum, NSCAN_BLK);
    k_scan3<<<NSCAN_BLK, 512, 0, s2>>>(cnt, incl, bsum, off, cursor, SEG);
    k_bin<<<(E + 255) / 256, 256, 0, s2>>>(h, r, t, cursor, binh, E);

    // ---- default stream: prep + layer-1 GEMM (split) ----
    k_wt2<<<(2 * NZ * DIM * DIM + 255) / 256, 256>>>(W1, root1, W2, root2, WH);
    k_cvt16<<<(n2 + 255) / 256, 256>>>((const float2*)x_emb, (uint32_t*)A16, n2);
    k_zero_out<<<1, DIM>>>(out);
    k_gemm_z<<<NRB, 256, GEMM_SMEM>>>(A16, WH, b1, Y16, acc, Nn, 0, 5);
    cudaEventRecord(evG1a, 0);
    k_gemm_z<<<NRB, 256, GEMM_SMEM>>>(A16, WH, b1, Y16, acc, Nn, 5, 9);

    // s2: partial agg (r0..3) concurrent with gemm1b
    cudaStreamWaitEvent(s2, evG1a, 0);
    k_agg<0><<<agg_blocks, 256, 0, s2>>>(Y16, off, binh, acc, nullptr, nullptr);
    cudaEventRecord(evA0, s2);

    // default: final agg layer1 (r4..7, relu -> A16), then layer-2 GEMM (split)
    cudaStreamWaitEvent(0, evA0, 0);
    k_agg<1><<<agg_blocks, 256>>>(Y16, off, binh, acc, (uint32_t*)A16, nullptr);
    k_gemm_z<<<NRB, 256, GEMM_SMEM>>>(A16, WH2, b2, Y16, acc, Nn, 0, 5);
    cudaEventRecord(evG2a, 0);
    k_gemm_z<<<NRB, 256, GEMM_SMEM>>>(A16, WH2, b2, Y16, acc, Nn, 5, 9);

    // s2: partial agg layer2 concurrent with gemm2b
    cudaStreamWaitEvent(s2, evG2a, 0);
    k_agg<0><<<agg_blocks, 256, 0, s2>>>(Y16, off, binh, acc, nullptr, nullptr);
    cudaEventRecord(evA1, s2);

    // default: final agg layer2 -> column mean -> out (join)
    cudaStreamWaitEvent(0, evA1, 0);
    k_agg<2><<<agg_blocks, 256>>>(Y16, off, binh, acc, nullptr, out);
}

// round 10
// speedup vs baseline: 1.0514x; 1.0514x over previous
#include <cuda_runtime.h>
#include <cuda_fp16.h>
#include <cstdint>

// Problem constants (fixed by the reference)
#define NNODES 50000
#define NREL   8
#define DIM    128
#define NEDGES 800000
#define NZ     9                       // z=0: root path, z=1..8: relations 0..7
#define MTILE  128
#define NRB    ((NNODES + MTILE - 1) / MTILE)   // 391 row blocks
#define SEG    (NREL * NNODES)         // 400000
#define NSCAN_BLK ((SEG + 511) / 512)  // 782

// full-K smem tiles viewed as u32 (half2): 64 u32/row padded to 68.
// ldmatrix: 8 rows spaced 68 u32 -> start banks 4r%32 = {0,4,...,28}, each row 4 banks
// -> all 32 banks covered, conflict-free.
#define KSTR 68
#define A_SM (MTILE * KSTR)
#define B_SM (MTILE * KSTR)
#define GEMM_SMEM ((A_SM + 2 * B_SM) * 4)   // 104448 B

// ---------------- scratch (static device globals; no allocation) ----------------
__device__ __half g_Y16[(size_t)NREL * NNODES * DIM];
__device__ float  g_acc[(size_t)NNODES * DIM];
__device__ __half g_A16[(size_t)NNODES * DIM];
__device__ __half g_WH[2 * NZ * DIM * DIM];   // [layer][z][n][k], z=0 root
__device__ int    g_cnt[SEG];
__device__ int    g_incl[SEG];
__device__ int    g_off[SEG + 1];
__device__ int    g_cursor[SEG];
__device__ int    g_binh[NEDGES];
__device__ int    g_bsum[1024];

// ---------------- helpers ----------------
__device__ __forceinline__ void mma_f16(float* c, const uint32_t* a, const uint32_t* b) {
    asm volatile(
        "mma.sync.aligned.m16n8k16.row.col.f32.f16.f16.f32 "
        "{%0,%1,%2,%3}, {%4,%5,%6,%7}, {%8,%9}, {%0,%1,%2,%3};"
        : "+f"(c[0]), "+f"(c[1]), "+f"(c[2]), "+f"(c[3])
        : "r"(a[0]), "r"(a[1]), "r"(a[2]), "r"(a[3]), "r"(b[0]), "r"(b[1]));
}
__device__ __forceinline__ void ldsm_x4(uint32_t& r0, uint32_t& r1, uint32_t& r2,
                                        uint32_t& r3, uint32_t addr) {
    asm volatile("ldmatrix.sync.aligned.m8n8.x4.shared.b16 {%0,%1,%2,%3}, [%4];"
                 : "=r"(r0), "=r"(r1), "=r"(r2), "=r"(r3) : "r"(addr));
}
__device__ __forceinline__ void cp_async16(uint32_t daddr, const void* src, int srcbytes) {
    asm volatile("cp.async.cg.shared.global [%0], [%1], 16, %2;"
                 :: "r"(daddr), "l"(src), "r"(srcbytes));
}
#define CP_COMMIT() asm volatile("cp.async.commit_group;" ::: "memory")
#define CP_WAIT1()  asm volatile("cp.async.wait_group 1;" ::: "memory")
#define CP_WAIT0()  asm volatile("cp.async.wait_group 0;" ::: "memory")

// ---------------- setup / binning kernels ----------------
__global__ void k_zero_cnt(int* __restrict__ cnt, int n) {
    int i = blockIdx.x * blockDim.x + threadIdx.x;
    if (i < n) cnt[i] = 0;
}
__global__ void k_count(const int* __restrict__ r, const int* __restrict__ t,
                        int* __restrict__ cnt, int E) {
    int e = blockIdx.x * blockDim.x + threadIdx.x;
    if (e < E) atomicAdd(&cnt[r[e] * NNODES + t[e]], 1);
}
__global__ void k_scan1(const int* __restrict__ cnt, int* __restrict__ incl,
                        int* __restrict__ bsum, int n) {
    __shared__ int sm[512];
    int tid = threadIdx.x;
    int gid = blockIdx.x * 512 + tid;
    sm[tid] = (gid < n) ? cnt[gid] : 0;
    __syncthreads();
#pragma unroll
    for (int d = 1; d < 512; d <<= 1) {
        int add = (tid >= d) ? sm[tid - d] : 0;
        __syncthreads();
        sm[tid] += add;
        __syncthreads();
    }
    if (gid < n) incl[gid] = sm[tid];
    if (tid == 511) bsum[blockIdx.x] = sm[511];
}
__global__ void k_scan2(int* __restrict__ bsum, int nb) {
    __shared__ int sm[1024];
    int tid = threadIdx.x;
    sm[tid] = (tid < nb) ? bsum[tid] : 0;
    __syncthreads();
#pragma unroll
    for (int d = 1; d < 1024; d <<= 1) {
        int add = (tid >= d) ? sm[tid - d] : 0;
        __syncthreads();
        sm[tid] += add;
        __syncthreads();
    }
    if (tid < nb) bsum[tid] = sm[tid];
}
__global__ void k_scan3(const int* __restrict__ cnt, const int* __restrict__ incl,
                        const int* __restrict__ bsum, int* __restrict__ off,
                        int* __restrict__ cursor, int n) {
    int gid = blockIdx.x * 512 + threadIdx.x;
    if (gid >= n) return;
    int base = (blockIdx.x > 0) ? bsum[blockIdx.x - 1] : 0;
    int ex = base + incl[gid] - cnt[gid];
    off[gid] = ex;
    cursor[gid] = ex;
    if (gid == n - 1) off[n] = base + incl[gid];
}
__global__ void k_bin(const int* __restrict__ h, const int* __restrict__ r,
                      const int* __restrict__ t, int* __restrict__ cursor,
                      int* __restrict__ binh, int E) {
    int e = blockIdx.x * blockDim.x + threadIdx.x;
    if (e >= E) return;
    int seg = r[e] * NNODES + t[e];
    int pos = atomicAdd(&cursor[seg], 1);
    binh[pos] = h[e];
}

// WH both layers: [layer][z][n][k]; z=0 -> root, z>=1 -> W[z-1]; transposed + fp16
__global__ void k_wt2(const float* __restrict__ W1, const float* __restrict__ root1,
                      const float* __restrict__ W2, const float* __restrict__ root2,
                      __half* __restrict__ dst) {
    int idx = blockIdx.x * blockDim.x + threadIdx.x;
    if (idx >= 2 * NZ * DIM * DIM) return;
    int zz = idx >> 14;
    int layer = zz / NZ, z = zz % NZ;
    int rem = idx & 16383;
    int n = rem >> 7, k = rem & 127;
    const float* src = (z == 0) ? (layer ? root2 : root1)
                                : ((layer ? W2 : W1) + ((size_t)(z - 1) << 14));
    dst[idx] = __float2half_rn(src[k * DIM + n]);
}

__global__ void k_cvt16(const float2* __restrict__ in, uint32_t* __restrict__ out, int n2) {
    int i = blockIdx.x * blockDim.x + threadIdx.x;
    if (i < n2) {
        float2 v = in[i];
        __half2 hv = __floats2half2_rn(v.x, v.y);
        out[i] = *(uint32_t*)&hv;
    }
}

// ---------------- z-loop fp16 GEMM with ldmatrix fragment loads ----------------
// One CTA owns a 128-row tile, loops z=0..8; A loaded once, B double-buffered.
// z==0 -> fp32 acc + bias; z>=1 -> fp16 Y[z-1].
__global__ __launch_bounds__(256, 2) void k_gemm_z(
    const __half* __restrict__ X, const __half* __restrict__ WH,
    const float* __restrict__ bias, __half* __restrict__ Y,
    float* __restrict__ acc, int Nn)
{
    extern __shared__ uint32_t sm[];
    uint32_t* As = sm;
    uint32_t* Bs = sm + A_SM;

    const int tid = threadIdx.x;
    const int wid = tid >> 5;
    const int lane = tid & 31;
    const int g = lane >> 2;
    const int q = lane & 3;
    const int warp_m = wid & 3;
    const int warp_n = wid >> 2;
    const int row0 = blockIdx.x * MTILE;

    const uint32_t abase = (uint32_t)__cvta_generic_to_shared(As);
    const uint32_t bbase = (uint32_t)__cvta_generic_to_shared(Bs);

    // ---- fill A tile ----
#pragma unroll
    for (int l = 0; l < 8; l++) {
        int lin = tid + 256 * l;
        int row = lin >> 4, seg = lin & 15;
        int gr = row0 + row;
        int ok = (gr < Nn) ? 16 : 0;
        int grc = (gr < Nn) ? gr : (Nn - 1);
        cp_async16(abase + (uint32_t)(row * KSTR + seg * 4) * 4,
                   X + (size_t)grc * DIM + seg * 8, ok);
    }
    CP_COMMIT();

    auto fill_B = [&](int buf, int z) {
        const __half* Bz = WH + ((size_t)z << 14);
        uint32_t base = bbase + (uint32_t)buf * B_SM * 4;
#pragma unroll
        for (int l = 0; l < 8; l++) {
            int lin = tid + 256 * l;
            int row = lin >> 4, seg = lin & 15;
            cp_async16(base + (uint32_t)(row * KSTR + seg * 4) * 4,
                       Bz + (size_t)row * DIM + seg * 8, 16);
        }
        CP_COMMIT();
    };
    fill_B(0, 0);

    // ---- ldmatrix lane base addresses (bytes, shared space) ----
    const int sub = lane >> 3;           // 0..3 address groups
    const int rin = lane & 7;
    uint32_t aAddr[2], bAddr[4];
#pragma unroll
    for (int mt = 0; mt < 2; mt++) {
        // m0: rows+0..7,k0 | m1: rows+8..15,k0 | m2: rows+0..7,k+16B | m3: rows+8..15,k+16B
        int row = warp_m * 32 + mt * 16 + (sub & 1) * 8 + rin;
        aAddr[mt] = abase + (uint32_t)(row * KSTR + (sub >> 1) * 4) * 4;
    }
#pragma unroll
    for (int p = 0; p < 4; p++) {
        // m0: n+0..7,k0 | m1: n+0..7,k+16B | m2: n+8..15,k0 | m3: n+8..15,k+16B
        int nrow = warp_n * 64 + p * 16 + (sub >> 1) * 8 + rin;
        bAddr[p] = bbase + (uint32_t)(nrow * KSTR + (sub & 1) * 4) * 4;
    }

#pragma unroll 1
    for (int z = 0; z < NZ; z++) {
        if (z < NZ - 1) { fill_B((z + 1) & 1, z + 1); CP_WAIT1(); }
        else            { CP_WAIT0(); }
        __syncthreads();

        const uint32_t bbuf = (uint32_t)(z & 1) * B_SM * 4;

        float cfrag[2][8][4];
#pragma unroll
        for (int mt = 0; mt < 2; mt++)
#pragma unroll
            for (int nt = 0; nt < 8; nt++)
#pragma unroll
                for (int i = 0; i < 4; i++) cfrag[mt][nt][i] = 0.0f;

#pragma unroll
        for (int ks = 0; ks < 8; ks++) {
            const uint32_t koff = (uint32_t)ks * 32;   // 16 halves = 32 B
            uint32_t a[2][4];
            ldsm_x4(a[0][0], a[0][1], a[0][2], a[0][3], aAddr[0] + koff);
            ldsm_x4(a[1][0], a[1][1], a[1][2], a[1][3], aAddr[1] + koff);
            uint32_t b[8][2];
#pragma unroll
            for (int p = 0; p < 4; p++)
                ldsm_x4(b[2 * p][0], b[2 * p][1], b[2 * p + 1][0], b[2 * p + 1][1],
                        bAddr[p] + bbuf + koff);
#pragma unroll
            for (int mt = 0; mt < 2; mt++)
#pragma unroll
                for (int nt = 0; nt < 8; nt++)
                    mma_f16(cfrag[mt][nt], a[mt], b[nt]);
        }
        __syncthreads();

        if (z >= 1) {
            __half* C = Y + (size_t)(z - 1) * Nn * DIM;
#pragma unroll
            for (int mt = 0; mt < 2; mt++)
#pragma unroll
                for (int half_ = 0; half_ < 2; half_++) {
                    int row = row0 + warp_m * 32 + mt * 16 + half_ * 8 + g;
                    if (row >= Nn) continue;
#pragma unroll
                    for (int nt = 0; nt < 8; nt++) {
                        int col = warp_n * 64 + nt * 8 + 2 * q;
                        __half2 hv = __floats2half2_rn(cfrag[mt][nt][half_ * 2 + 0],
                                                       cfrag[mt][nt][half_ * 2 + 1]);
                        *(uint32_t*)&C[(size_t)row * DIM + col] = *(uint32_t*)&hv;
                    }
                }
        } else {
#pragma unroll
            for (int mt = 0; mt < 2; mt++)
#pragma unroll
                for (int half_ = 0; half_ < 2; half_++) {
                    int row = row0 + warp_m * 32 + mt * 16 + half_ * 8 + g;
                    if (row >= Nn) continue;
#pragma unroll
                    for (int nt = 0; nt < 8; nt++) {
                        int col = warp_n * 64 + nt * 8 + 2 * q;
                        float2 v;
                        v.x = cfrag[mt][nt][half_ * 2 + 0] + bias[col];
                        v.y = cfrag[mt][nt][half_ * 2 + 1] + bias[col + 1];
                        *(float2*)&acc[(size_t)row * DIM + col] = v;
                    }
                }
        }
    }
}

// ---------------- aggregation: one warp per target node, atomic-free ----------------
// MODE 0: relu(acc + sum_r mean) -> fp16 A16.
// MODE 1: block-reduced column mean of (acc + sum_r mean) -> atomicAdd out.
template <int MODE>
__global__ __launch_bounds__(256) void k_agg(
    const __half* __restrict__ Y, const int* __restrict__ off,
    const int* __restrict__ binh, const float* __restrict__ accin,
    uint32_t* __restrict__ out16, float* __restrict__ outf)
{
    __shared__ float bsum[8][DIM];
    const int wid = threadIdx.x >> 5;
    const int lane = threadIdx.x & 31;
    const int t = blockIdx.x * 8 + wid;        // NNODES % 8 == 0

    float4 a4 = ((const float4*)(accin + (size_t)t * DIM))[lane];

#pragma unroll
    for (int rr = 0; rr < NREL; rr++) {
        int seg = rr * NNODES + t;
        int s = __ldg(&off[seg]);
        int e = __ldg(&off[seg + 1]);
        if (e > s) {
            float4 sum = make_float4(0.f, 0.f, 0.f, 0.f);
            const __half* Yr = Y + (size_t)rr * NNODES * DIM;
            for (int i = s; i < e; i++) {
                int hh = __ldg(&binh[i]);
                uint2 v = ((const uint2*)(Yr + (size_t)hh * DIM))[lane];
                __half2* hp = (__half2*)&v;
                float2 f0 = __half22float2(hp[0]);
                float2 f1 = __half22float2(hp[1]);
                sum.x += f0.x; sum.y += f0.y; sum.z += f1.x; sum.w += f1.y;
            }
            float w = 1.0f / (float)(e - s);
            a4.x += sum.x * w; a4.y += sum.y * w;
            a4.z += sum.z * w; a4.w += sum.w * w;
        }
    }

    if (MODE == 0) {
        __half2 h0 = __floats2half2_rn(fmaxf(a4.x, 0.f), fmaxf(a4.y, 0.f));
        __half2 h1 = __floats2half2_rn(fmaxf(a4.z, 0.f), fmaxf(a4.w, 0.f));
        uint2 o;
        o.x = *(uint32_t*)&h0;
        o.y = *(uint32_t*)&h1;
        ((uint2*)(out16 + (size_t)t * (DIM / 2)))[lane] = o;
    } else {
        bsum[wid][lane * 4 + 0] = a4.x;
        bsum[wid][lane * 4 + 1] = a4.y;
        bsum[wid][lane * 4 + 2] = a4.z;
        bsum[wid][lane * 4 + 3] = a4.w;
        __syncthreads();
        int c = threadIdx.x;
        if (c < DIM) {
            float s = 0.0f;
#pragma unroll
            for (int w2 = 0; w2 < 8; w2++) s += bsum[w2][c];
            atomicAdd(&outf[c], s * (1.0f / (float)NNODES));
        }
    }
}

__global__ void k_zero_out(float* __restrict__ out) { out[threadIdx.x] = 0.0f; }

// ---------------- launch ----------------
extern "C" void kernel_launch(void* const* d_in, const int* in_sizes, int n_in,
                              void* d_out, int out_size) {
    const int*   h     = (const int*)d_in[0];
    const int*   r     = (const int*)d_in[1];
    const int*   t     = (const int*)d_in[2];
    const float* x_emb = (const float*)d_in[3];
    const float* W1    = (const float*)d_in[4];
    const float* root1 = (const float*)d_in[5];
    const float* b1    = (const float*)d_in[6];
    const float* W2    = (const float*)d_in[7];
    const float* root2 = (const float*)d_in[8];
    const float* b2    = (const float*)d_in[9];
    float* out = (float*)d_out;

    __half *Y16, *A16, *WH;
    float *acc;
    int *cnt, *incl, *off, *cursor, *binh, *bsum;
    cudaGetSymbolAddress((void**)&Y16,    g_Y16);
    cudaGetSymbolAddress((void**)&acc,    g_acc);
    cudaGetSymbolAddress((void**)&A16,    g_A16);
    cudaGetSymbolAddress((void**)&WH,     g_WH);
    cudaGetSymbolAddress((void**)&cnt,    g_cnt);
    cudaGetSymbolAddress((void**)&incl,   g_incl);
    cudaGetSymbolAddress((void**)&off,    g_off);
    cudaGetSymbolAddress((void**)&cursor, g_cursor);
    cudaGetSymbolAddress((void**)&binh,   g_binh);
    cudaGetSymbolAddress((void**)&bsum,   g_bsum);

    const int E = NEDGES, Nn = NNODES;
    const int n2 = Nn * DIM / 2;
    const int agg_blocks = Nn / 8;   // 6250
    const __half* WH2 = WH + (size_t)NZ * DIM * DIM;

    // one-time resources (created on the first, uncaptured call; reused under capture)
    static cudaStream_t s2 = nullptr;
    static cudaEvent_t evFork, evCSR;
    if (!s2) {
        cudaFuncSetAttribute(k_gemm_z, cudaFuncAttributeMaxDynamicSharedMemorySize, GEMM_SMEM);
        cudaStreamCreateWithFlags(&s2, cudaStreamNonBlocking);
        cudaEventCreateWithFlags(&evFork, cudaEventDisableTiming);
        cudaEventCreateWithFlags(&evCSR,  cudaEventDisableTiming);
    }

    // ---- fork: CSR build on s2, hidden behind prep + layer-1 GEMM ----
    cudaEventRecord(evFork, 0);
    cudaStreamWaitEvent(s2, evFork, 0);
    k_zero_cnt<<<(SEG + 255) / 256, 256, 0, s2>>>(cnt, SEG);
    k_count<<<(E + 255) / 256, 256, 0, s2>>>(r, t, cnt, E);
    k_scan1<<<NSCAN_BLK, 512, 0, s2>>>(cnt, incl, bsum, SEG);
    k_scan2<<<1, 1024, 0, s2>>>(bsum, NSCAN_BLK);
    k_scan3<<<NSCAN_BLK, 512, 0, s2>>>(cnt, incl, bsum, off, cursor, SEG);
    k_bin<<<(E + 255) / 256, 256, 0, s2>>>(h, r, t, cursor, binh, E);
    cudaEventRecord(evCSR, s2);

    // ---- main stream ----
    k_wt2<<<(2 * NZ * DIM * DIM + 255) / 256, 256>>>(W1, root1, W2, root2, WH);
    k_cvt16<<<(n2 + 255) / 256, 256>>>((const float2*)x_emb, (uint32_t*)A16, n2);
    k_zero_out<<<1, DIM>>>(out);
    k_gemm_z<<<NRB, 256, GEMM_SMEM>>>(A16, WH, b1, Y16, acc, Nn);

    cudaStreamWaitEvent(0, evCSR, 0);   // join CSR before aggregation
    k_agg<0><<<agg_blocks, 256>>>(Y16, off, binh, acc, (uint32_t*)A16, nullptr);

    k_gemm_z<<<NRB, 256, GEMM_SMEM>>>(A16, WH2, b2, Y16, acc, Nn);
    k_agg<1><<<agg_blocks, 256>>>(Y16, off, binh, acc, nullptr, out);
}

// round 11
// speedup vs baseline: 1.3485x; 1.2826x over previous
#include <cuda_runtime.h>
#include <cuda_fp16.h>
#include <cstdint>

// Problem constants (fixed by the reference)
#define NNODES 50000
#define NREL   8
#define DIM    128
#define NEDGES 800000
#define NZ     9                       // z=0: root path, z=1..8: relations 0..7
#define MTILE  128
#define NRB    ((NNODES + MTILE - 1) / MTILE)   // 391 row blocks
#define SEG    (NREL * NNODES)         // 400000
#define NSCAN_BLK ((SEG + 511) / 512)  // 782

// K = 9*128 = 1152, chunked by BK=64 halves (32 u32). Row stride 36 u32 (pad 4):
// ldmatrix 8 rows spaced 36 u32 -> start banks 4r%32 = {0,4,...,28}, 4 banks/row
// -> all 32 banks covered, conflict-free.
#define NCHUNK 18
#define CSTR   36
#define A_CH   (MTILE * CSTR)          // 4608 u32 = 18432 B
#define GEMM_SMEM (4 * A_CH * 4)       // A[2] + B[2] = 73728 B

// ---------------- scratch (static device globals; no allocation) ----------------
__device__ __half g_M16[(size_t)NREL * NNODES * DIM]; // per-relation aggregated means (fp16)
__device__ __half g_A16[(size_t)NNODES * DIM];        // layer-1 input (fp16)
__device__ __half g_B16[(size_t)NNODES * DIM];        // layer-1 output = layer-2 input (fp16)
__device__ __half g_WH[2 * NZ * DIM * DIM];           // [layer][z][n][k], z=0 root
__device__ int    g_cnt[SEG];
__device__ int    g_incl[SEG];
__device__ int    g_off[SEG + 1];
__device__ int    g_cursor[SEG];
__device__ int    g_binh[NEDGES];
__device__ int    g_bsum[1024];

// ---------------- helpers ----------------
__device__ __forceinline__ void mma_f16(float* c, const uint32_t* a, const uint32_t* b) {
    asm volatile(
        "mma.sync.aligned.m16n8k16.row.col.f32.f16.f16.f32 "
        "{%0,%1,%2,%3}, {%4,%5,%6,%7}, {%8,%9}, {%0,%1,%2,%3};"
        : "+f"(c[0]), "+f"(c[1]), "+f"(c[2]), "+f"(c[3])
        : "r"(a[0]), "r"(a[1]), "r"(a[2]), "r"(a[3]), "r"(b[0]), "r"(b[1]));
}
__device__ __forceinline__ void ldsm_x4(uint32_t& r0, uint32_t& r1, uint32_t& r2,
                                        uint32_t& r3, uint32_t addr) {
    asm volatile("ldmatrix.sync.aligned.m8n8.x4.shared.b16 {%0,%1,%2,%3}, [%4];"
                 : "=r"(r0), "=r"(r1), "=r"(r2), "=r"(r3) : "r"(addr));
}
__device__ __forceinline__ void cp_async16(uint32_t daddr, const void* src, int srcbytes) {
    asm volatile("cp.async.cg.shared.global [%0], [%1], 16, %2;"
                 :: "r"(daddr), "l"(src), "r"(srcbytes));
}
#define CP_COMMIT() asm volatile("cp.async.commit_group;" ::: "memory")
#define CP_WAIT1()  asm volatile("cp.async.wait_group 1;" ::: "memory")
#define CP_WAIT0()  asm volatile("cp.async.wait_group 0;" ::: "memory")

// ---------------- setup / binning kernels ----------------
__global__ void k_zero_cnt(int* __restrict__ cnt, int n) {
    int i = blockIdx.x * blockDim.x + threadIdx.x;
    if (i < n) cnt[i] = 0;
}
__global__ void k_count(const int* __restrict__ r, const int* __restrict__ t,
                        int* __restrict__ cnt, int E) {
    int e = blockIdx.x * blockDim.x + threadIdx.x;
    if (e < E) atomicAdd(&cnt[r[e] * NNODES + t[e]], 1);
}
__global__ void k_scan1(const int* __restrict__ cnt, int* __restrict__ incl,
                        int* __restrict__ bsum, int n) {
    __shared__ int sm[512];
    int tid = threadIdx.x;
    int gid = blockIdx.x * 512 + tid;
    sm[tid] = (gid < n) ? cnt[gid] : 0;
    __syncthreads();
#pragma unroll
    for (int d = 1; d < 512; d <<= 1) {
        int add = (tid >= d) ? sm[tid - d] : 0;
        __syncthreads();
        sm[tid] += add;
        __syncthreads();
    }
    if (gid < n) incl[gid] = sm[tid];
    if (tid == 511) bsum[blockIdx.x] = sm[511];
}
__global__ void k_scan2(int* __restrict__ bsum, int nb) {
    __shared__ int sm[1024];
    int tid = threadIdx.x;
    sm[tid] = (tid < nb) ? bsum[tid] : 0;
    __syncthreads();
#pragma unroll
    for (int d = 1; d < 1024; d <<= 1) {
        int add = (tid >= d) ? sm[tid - d] : 0;
        __syncthreads();
        sm[tid] += add;
        __syncthreads();
    }
    if (tid < nb) bsum[tid] = sm[tid];
}
__global__ void k_scan3(const int* __restrict__ cnt, const int* __restrict__ incl,
                        const int* __restrict__ bsum, int* __restrict__ off,
                        int* __restrict__ cursor, int n) {
    int gid = blockIdx.x * 512 + threadIdx.x;
    if (gid >= n) return;
    int base = (blockIdx.x > 0) ? bsum[blockIdx.x - 1] : 0;
    int ex = base + incl[gid] - cnt[gid];
    off[gid] = ex;
    cursor[gid] = ex;
    if (gid == n - 1) off[n] = base + incl[gid];
}
__global__ void k_bin(const int* __restrict__ h, const int* __restrict__ r,
                      const int* __restrict__ t, int* __restrict__ cursor,
                      int* __restrict__ binh, int E) {
    int e = blockIdx.x * blockDim.x + threadIdx.x;
    if (e >= E) return;
    int seg = r[e] * NNODES + t[e];
    int pos = atomicAdd(&cursor[seg], 1);
    binh[pos] = h[e];
}

// WH both layers: [layer][z][n][k]; z=0 -> root, z>=1 -> W[z-1]; transposed + fp16
__global__ void k_wt2(const float* __restrict__ W1, const float* __restrict__ root1,
                      const float* __restrict__ W2, const float* __restrict__ root2,
                      __half* __restrict__ dst) {
    int idx = blockIdx.x * blockDim.x + threadIdx.x;
    if (idx >= 2 * NZ * DIM * DIM) return;
    int zz = idx >> 14;
    int layer = zz / NZ, z = zz % NZ;
    int rem = idx & 16383;
    int n = rem >> 7, k = rem & 127;
    const float* src = (z == 0) ? (layer ? root2 : root1)
                                : ((layer ? W2 : W1) + ((size_t)(z - 1) << 14));
    dst[idx] = __float2half_rn(src[k * DIM + n]);
}

__global__ void k_cvt16(const float2* __restrict__ in, uint32_t* __restrict__ out, int n2) {
    int i = blockIdx.x * blockDim.x + threadIdx.x;
    if (i < n2) {
        float2 v = in[i];
        __half2 hv = __floats2half2_rn(v.x, v.y);
        out[i] = *(uint32_t*)&hv;
    }
}

// ---------------- aggregate-first: M16[r][t] = mean over seg(r,t) of X16[h] ----------------
// One warp per target node; gather table is 12.8 MB (L2-resident). Empty segs -> zeros.
__global__ __launch_bounds__(256) void k_aggF(
    const __half* __restrict__ X16, const int* __restrict__ off,
    const int* __restrict__ binh, __half* __restrict__ M16)
{
    const int wid = threadIdx.x >> 5;
    const int lane = threadIdx.x & 31;
    const int t = blockIdx.x * 8 + wid;        // NNODES % 8 == 0

#pragma unroll
    for (int rr = 0; rr < NREL; rr++) {
        int seg = rr * NNODES + t;
        int s = __ldg(&off[seg]);
        int e = __ldg(&off[seg + 1]);
        float4 sum = make_float4(0.f, 0.f, 0.f, 0.f);
        if (e > s) {
            for (int i = s; i < e; i++) {
                int hh = __ldg(&binh[i]);
                uint2 v = ((const uint2*)(X16 + (size_t)hh * DIM))[lane];
                __half2* hp = (__half2*)&v;
                float2 f0 = __half22float2(hp[0]);
                float2 f1 = __half22float2(hp[1]);
                sum.x += f0.x; sum.y += f0.y; sum.z += f1.x; sum.w += f1.y;
            }
            float w = 1.0f / (float)(e - s);
            sum.x *= w; sum.y *= w; sum.z *= w; sum.w *= w;
        }
        __half2 h0 = __floats2half2_rn(sum.x, sum.y);
        __half2 h1 = __floats2half2_rn(sum.z, sum.w);
        uint2 o;
        o.x = *(uint32_t*)&h0;
        o.y = *(uint32_t*)&h1;
        ((uint2*)(M16 + (size_t)seg * DIM))[lane] = o;
    }
}

// ---------------- fused K=1152 GEMM: out = [X | M_1..M_8] @ WH + epilogue ----------------
// MODE 0: h = relu(gemm + bias) -> fp16 out16.
// MODE 1: column-mean of gemm rows atomically accumulated into outf (pre-init to b2).
template <int MODE>
__global__ __launch_bounds__(256, 2) void k_gemmF(
    const __half* __restrict__ X, const __half* __restrict__ M,
    const __half* __restrict__ WH, const float* __restrict__ bias,
    __half* __restrict__ out16, float* __restrict__ outf, int Nn)
{
    extern __shared__ uint32_t smb[];
    uint32_t* As = smb;                 // [2][A_CH]
    uint32_t* Bs = smb + 2 * A_CH;      // [2][A_CH]
    float* scol = (float*)smb;          // reused after mainloop (MODE 1)

    const int tid = threadIdx.x;
    const int wid = tid >> 5;
    const int lane = tid & 31;
    const int g = lane >> 2;
    const int q = lane & 3;
    const int warp_m = wid & 3;
    const int warp_n = wid >> 2;
    const int row0 = blockIdx.x * MTILE;

    const uint32_t abase = (uint32_t)__cvta_generic_to_shared(As);
    const uint32_t bbase = (uint32_t)__cvta_generic_to_shared(Bs);

    auto fill_chunk = [&](int buf, int c) {
        int z = c >> 1, hc = c & 1;
        const __half* srcA = (z == 0) ? X : (M + (size_t)(z - 1) * Nn * DIM);
        const __half* srcB = WH + ((size_t)z << 14) + hc * 64;
        uint32_t ab = abase + (uint32_t)buf * A_CH * 4;
        uint32_t bb = bbase + (uint32_t)buf * A_CH * 4;
#pragma unroll
        for (int l = 0; l < 4; l++) {
            int lin = tid + 256 * l;
            int row = lin >> 3, seg = lin & 7;
            int gr = row0 + row;
            int ok = (gr < Nn) ? 16 : 0;
            int grc = (gr < Nn) ? gr : (Nn - 1);
            cp_async16(ab + (uint32_t)(row * CSTR + seg * 4) * 4,
                       srcA + (size_t)grc * DIM + hc * 64 + seg * 8, ok);
        }
#pragma unroll
        for (int l = 0; l < 4; l++) {
            int lin = tid + 256 * l;
            int row = lin >> 3, seg = lin & 7;
            cp_async16(bb + (uint32_t)(row * CSTR + seg * 4) * 4,
                       srcB + (size_t)row * DIM + seg * 8, 16);
        }
        CP_COMMIT();
    };
    fill_chunk(0, 0);

    // ldmatrix lane base addresses (relative; buffer offset added at use)
    const int sub = lane >> 3;
    const int rin = lane & 7;
    uint32_t aAddr[2], bAddr[4];
#pragma unroll
    for (int mt = 0; mt < 2; mt++) {
        int row = warp_m * 32 + mt * 16 + (sub & 1) * 8 + rin;
        aAddr[mt] = abase + (uint32_t)(row * CSTR + (sub >> 1) * 4) * 4;
    }
#pragma unroll
    for (int p = 0; p < 4; p++) {
        int nrow = warp_n * 64 + p * 16 + (sub >> 1) * 8 + rin;
        bAddr[p] = bbase + (uint32_t)(nrow * CSTR + (sub & 1) * 4) * 4;
    }

    float cfrag[2][8][4];
#pragma unroll
    for (int mt = 0; mt < 2; mt++)
#pragma unroll
        for (int nt = 0; nt < 8; nt++)
#pragma unroll
            for (int i = 0; i < 4; i++) cfrag[mt][nt][i] = 0.0f;

#pragma unroll 1
    for (int c = 0; c < NCHUNK; c++) {
        if (c < NCHUNK - 1) { fill_chunk((c + 1) & 1, c + 1); CP_WAIT1(); }
        else                { CP_WAIT0(); }
        __syncthreads();

        const uint32_t boff = (uint32_t)(c & 1) * A_CH * 4;

#pragma unroll
        for (int ks = 0; ks < 4; ks++) {
            const uint32_t koff = boff + (uint32_t)ks * 32;
            uint32_t a[2][4];
            ldsm_x4(a[0][0], a[0][1], a[0][2], a[0][3], aAddr[0] + koff);
            ldsm_x4(a[1][0], a[1][1], a[1][2], a[1][3], aAddr[1] + koff);
            uint32_t b[8][2];
#pragma unroll
            for (int p = 0; p < 4; p++)
                ldsm_x4(b[2 * p][0], b[2 * p][1], b[2 * p + 1][0], b[2 * p + 1][1],
                        bAddr[p] + koff);
#pragma unroll
            for (int mt = 0; mt < 2; mt++)
#pragma unroll
                for (int nt = 0; nt < 8; nt++)
                    mma_f16(cfrag[mt][nt], a[mt], b[nt]);
        }
        __syncthreads();
    }

    if (MODE == 0) {
        // h = relu(gemm + bias) -> fp16
#pragma unroll
        for (int mt = 0; mt < 2; mt++)
#pragma unroll
            for (int half_ = 0; half_ < 2; half_++) {
                int row = row0 + warp_m * 32 + mt * 16 + half_ * 8 + g;
                if (row >= Nn) continue;
#pragma unroll
                for (int nt = 0; nt < 8; nt++) {
                    int col = warp_n * 64 + nt * 8 + 2 * q;
                    float vx = cfrag[mt][nt][half_ * 2 + 0] + bias[col];
                    float vy = cfrag[mt][nt][half_ * 2 + 1] + bias[col + 1];
                    __half2 hv = __floats2half2_rn(fmaxf(vx, 0.f), fmaxf(vy, 0.f));
                    *(uint32_t*)&out16[(size_t)row * DIM + col] = *(uint32_t*)&hv;
                }
            }
    } else {
        // column sums over this CTA's rows (OOB rows are exactly zero via zfill)
        float rs[8][2];
#pragma unroll
        for (int nt = 0; nt < 8; nt++)
#pragma unroll
            for (int p = 0; p < 2; p++)
                rs[nt][p] = cfrag[0][nt][p] + cfrag[0][nt][2 + p]
                          + cfrag[1][nt][p] + cfrag[1][nt][2 + p];
        // reduce over g (lane bits 2..4)
#pragma unroll
        for (int nt = 0; nt < 8; nt++)
#pragma unroll
            for (int p = 0; p < 2; p++) {
                rs[nt][p] += __shfl_xor_sync(0xffffffff, rs[nt][p], 4);
                rs[nt][p] += __shfl_xor_sync(0xffffffff, rs[nt][p], 8);
                rs[nt][p] += __shfl_xor_sync(0xffffffff, rs[nt][p], 16);
            }
        if (tid < DIM) scol[tid] = 0.0f;
        __syncthreads();
        if (lane < 4) {
#pragma unroll
            for (int nt = 0; nt < 8; nt++)
#pragma unroll
                for (int p = 0; p < 2; p++) {
                    int col = warp_n * 64 + nt * 8 + 2 * lane + p;
                    atomicAdd(&scol[col], rs[nt][p]);
                }
        }
        __syncthreads();
        if (tid < DIM)
            atomicAdd(&outf[tid], scol[tid] * (1.0f / (float)NNODES));
    }
}

__global__ void k_init_out(float* __restrict__ out, const float* __restrict__ b2) {
    out[threadIdx.x] = b2[threadIdx.x];
}

// ---------------- launch ----------------
extern "C" void kernel_launch(void* const* d_in, const int* in_sizes, int n_in,
                              void* d_out, int out_size) {
    const int*   h     = (const int*)d_in[0];
    const int*   r     = (const int*)d_in[1];
    const int*   t     = (const int*)d_in[2];
    const float* x_emb = (const float*)d_in[3];
    const float* W1    = (const float*)d_in[4];
    const float* root1 = (const float*)d_in[5];
    const float* b1    = (const float*)d_in[6];
    const float* W2    = (const float*)d_in[7];
    const float* root2 = (const float*)d_in[8];
    const float* b2    = (const float*)d_in[9];
    float* out = (float*)d_out;

    __half *M16, *A16, *B16, *WH;
    int *cnt, *incl, *off, *cursor, *binh, *bsum;
    cudaGetSymbolAddress((void**)&M16,    g_M16);
    cudaGetSymbolAddress((void**)&A16,    g_A16);
    cudaGetSymbolAddress((void**)&B16,    g_B16);
    cudaGetSymbolAddress((void**)&WH,     g_WH);
    cudaGetSymbolAddress((void**)&cnt,    g_cnt);
    cudaGetSymbolAddress((void**)&incl,   g_incl);
    cudaGetSymbolAddress((void**)&off,    g_off);
    cudaGetSymbolAddress((void**)&cursor, g_cursor);
    cudaGetSymbolAddress((void**)&binh,   g_binh);
    cudaGetSymbolAddress((void**)&bsum,   g_bsum);

    const int E = NEDGES, Nn = NNODES;
    const int n2 = Nn * DIM / 2;
    const int agg_blocks = Nn / 8;   // 6250
    const __half* WH2 = WH + (size_t)NZ * DIM * DIM;

    // one-time resources (created on the first, uncaptured call; reused under capture)
    static cudaStream_t s2 = nullptr;
    static cudaEvent_t evFork, evCSR;
    if (!s2) {
        cudaFuncSetAttribute(k_gemmF<0>, cudaFuncAttributeMaxDynamicSharedMemorySize, GEMM_SMEM);
        cudaFuncSetAttribute(k_gemmF<1>, cudaFuncAttributeMaxDynamicSharedMemorySize, GEMM_SMEM);
        cudaStreamCreateWithFlags(&s2, cudaStreamNonBlocking);
        cudaEventCreateWithFlags(&evFork, cudaEventDisableTiming);
        cudaEventCreateWithFlags(&evCSR,  cudaEventDisableTiming);
    }

    // ---- fork: CSR build on s2, overlapping prep on main stream ----
    cudaEventRecord(evFork, 0);
    cudaStreamWaitEvent(s2, evFork, 0);
    k_zero_cnt<<<(SEG + 255) / 256, 256, 0, s2>>>(cnt, SEG);
    k_count<<<(E + 255) / 256, 256, 0, s2>>>(r, t, cnt, E);
    k_scan1<<<NSCAN_BLK, 512, 0, s2>>>(cnt, incl, bsum, SEG);
    k_scan2<<<1, 1024, 0, s2>>>(bsum, NSCAN_BLK);
    k_scan3<<<NSCAN_BLK, 512, 0, s2>>>(cnt, incl, bsum, off, cursor, SEG);
    k_bin<<<(E + 255) / 256, 256, 0, s2>>>(h, r, t, cursor, binh, E);
    cudaEventRecord(evCSR, s2);

    // ---- main stream: prep ----
    k_wt2<<<(2 * NZ * DIM * DIM + 255) / 256, 256>>>(W1, root1, W2, root2, WH);
    k_cvt16<<<(n2 + 255) / 256, 256>>>((const float2*)x_emb, (uint32_t*)A16, n2);
    k_init_out<<<1, DIM>>>(out, b2);

    cudaStreamWaitEvent(0, evCSR, 0);   // CSR needed from here on

    // ---- layer 1: aggregate-first, then fused K=1152 GEMM (relu -> B16) ----
    k_aggF<<<agg_blocks, 256>>>(A16, off, binh, M16);
    k_gemmF<0><<<NRB, 256, GEMM_SMEM>>>(A16, M16, WH, b1, B16, nullptr, Nn);

    // ---- layer 2: aggregate, then fused GEMM with in-epilogue column mean ----
    k_aggF<<<agg_blocks, 256>>>(B16, off, binh, M16);
    k_gemmF<1><<<NRB, 256, GEMM_SMEM>>>(B16, M16, WH2, nullptr, nullptr, out, Nn);
}